// round 4
// baseline (speedup 1.0000x reference)
#include <cuda_runtime.h>
#include <cuda_fp16.h>
#include <cstdint>

#define DI __device__ __forceinline__

// ---------------- problem constants ----------------
namespace {
constexpr int I_DIM   = 512;
constexpr int O_DIM   = 512;
constexpr int NDEG    = 8;               // degrees 1..8 in the GEMM; d=0 -> bias
constexpr int KTOT    = NDEG * I_DIM;    // 4096
constexpr int M_TILE  = 128;
constexpr int KBLK    = 64;              // one i-block (A-plane width)
constexpr int NUM_IB  = I_DIM / KBLK;    // 8
constexpr int THREADS = 512;             // 16 warps: warp_m = wid&3, warp_n = wid>>2

constexpr int KT32     = 32;             // B pipeline tile: 32 k-rows x 512 cols
constexpr int NTILES   = KTOT / KT32;    // 128
constexpr int B_STAGES = 3;

constexpr float B_SCALE    = 512.0f;
constexpr float B_INVSCALE = 1.0f / 512.0f;

// smem: A planes: 8 x (128 rows x 128B) = 131072 ; B ring: 3 x 32768 = 98304
constexpr int SM_A       = 0;
constexpr int SM_B       = 131072;
constexpr int SM_USED    = SM_B + B_STAGES * 32768;   // 229376
constexpr int SMEM_BYTES = SM_USED + 1024;            // 230400 (<= 232448 max)
}

// ---------------- device scratch ----------------
// g_B[k][n], k = (d-1)*512 + i  (4096 x 512 fp16, pre-scaled by 512)
__device__ __align__(128) __half g_B[KTOT * O_DIM];
__device__ float g_bias[O_DIM];

// ---------------- helpers ----------------
DI uint32_t smem_u32(const void* p) {
    uint32_t a;
    asm("{ .reg .u64 t; cvta.to.shared.u64 t, %1; cvt.u32.u64 %0, t; }" : "=r"(a) : "l"(p));
    return a;
}
DI uint32_t swzA(uint32_t off) { return off ^ ((off >> 3) & 0x70); } // 128B rows
DI uint32_t swzB(uint32_t off) { return off ^ ((off >> 6) & 0x70); } // 1024B rows

DI void cpa16(uint32_t dst, const void* src) {
    asm volatile("cp.async.cg.shared.global [%0], [%1], 16;" :: "r"(dst), "l"(src) : "memory");
}
DI void cpa_commit() { asm volatile("cp.async.commit_group;" ::: "memory"); }
DI void cpa_wait2()  { asm volatile("cp.async.wait_group 2;" ::: "memory"); }

DI void sts128(uint32_t a, uint32_t r0, uint32_t r1, uint32_t r2, uint32_t r3) {
    asm volatile("st.shared.v4.b32 [%0], {%1,%2,%3,%4};"
                 :: "r"(a), "r"(r0), "r"(r1), "r"(r2), "r"(r3) : "memory");
}
DI void ldsm_x4(uint32_t& r0, uint32_t& r1, uint32_t& r2, uint32_t& r3, uint32_t addr) {
    asm volatile("ldmatrix.sync.aligned.m8n8.x4.shared.b16 {%0,%1,%2,%3}, [%4];"
                 : "=r"(r0), "=r"(r1), "=r"(r2), "=r"(r3) : "r"(addr));
}
DI void ldsm_x4_t(uint32_t& r0, uint32_t& r1, uint32_t& r2, uint32_t& r3, uint32_t addr) {
    asm volatile("ldmatrix.sync.aligned.m8n8.x4.trans.shared.b16 {%0,%1,%2,%3}, [%4];"
                 : "=r"(r0), "=r"(r1), "=r"(r2), "=r"(r3) : "r"(addr));
}
DI void mma16816(float& c0, float& c1, float& c2, float& c3,
                 uint32_t a0, uint32_t a1, uint32_t a2, uint32_t a3,
                 uint32_t b0, uint32_t b1) {
    asm volatile("mma.sync.aligned.m16n8k16.row.col.f32.f16.f16.f32 "
                 "{%0,%1,%2,%3}, {%4,%5,%6,%7}, {%8,%9}, {%0,%1,%2,%3};"
                 : "+f"(c0), "+f"(c1), "+f"(c2), "+f"(c3)
                 : "r"(a0), "r"(a1), "r"(a2), "r"(a3), "r"(b0), "r"(b1));
}

// tanh via ex2/rcp: abs err ~1e-6, << fp16 feature quantization
DI float fast_tanh(float v) {
    float f = fminf(fmaxf(v, -15.f), 15.f) * 2.8853900817779268f; // 2*log2(e)
    float e; asm("ex2.approx.f32 %0, %1;" : "=f"(e) : "f"(f));
    float r; asm("rcp.approx.f32 %0, %1;" : "=f"(r) : "f"(e + 1.f));
    return (e - 1.f) * r;
}

// ---------------- prologue kernels ----------------
// C layout: C[i][n][d], 9 floats per (i,n)
__global__ void prep_b_kernel(const float* __restrict__ C) {
    int tid = blockIdx.x * blockDim.x + threadIdx.x;   // one (i,n) each
    int n = tid & (O_DIM - 1);
    int i = tid >> 9;
    const float* src = C + ((size_t)i * O_DIM + n) * 9;
    #pragma unroll
    for (int d = 1; d <= NDEG; d++)
        g_B[(size_t)((d - 1) * I_DIM + i) * O_DIM + n] = __float2half_rn(src[d] * B_SCALE);
}
__global__ void bias_kernel(const float* __restrict__ C) {
    int gw  = (blockIdx.x * blockDim.x + threadIdx.x) >> 5;
    int lid = threadIdx.x & 31;
    float s = 0.f;
    for (int i = lid; i < I_DIM; i += 32)
        s += C[((size_t)i * O_DIM + gw) * 9];
    #pragma unroll
    for (int o = 16; o; o >>= 1) s += __shfl_xor_sync(0xffffffffu, s, o);
    if (lid == 0) g_bias[gw] = s;
}

// ---------------- main fused kernel ----------------
__global__ void __launch_bounds__(THREADS, 1)
legendre_main(const float* __restrict__ x, float* __restrict__ out) {
    extern __shared__ char smem_raw[];
    const uint32_t sb  = (smem_u32(smem_raw) + 1023u) & ~1023u;
    const uint32_t sbA = sb + SM_A;
    const uint32_t sbB = sb + SM_B;

    const int tid = threadIdx.x;
    const int lid = tid & 31;
    const int wid = tid >> 5;
    const int warp_m = wid & 3;        // 32-row slab
    const int warp_n = wid >> 2;       // 0..3 -> 128-col slab
    const int r0 = blockIdx.x * M_TILE;

    const int la_row = lid & 15;
    const int la_hi  = lid >> 4;

    // ---- B tile loader: tile t = 32 k-rows x 512 cols (32KB), ring stage t%3 ----
    auto prefetch_B = [&](int t) {
        const int dd   = (t >> 1) & 7;
        const int ib   = t >> 4;
        const int hv   = t & 1;
        const int krow0 = dd * I_DIM + ib * KBLK + hv * KT32;
        const uint32_t dst = sbB + (uint32_t)(t % B_STAGES) * 32768;
        #pragma unroll
        for (int q = 0; q < 4; q++) {
            int ch  = tid + q * THREADS;
            int row = ch >> 6, cc = ch & 63;
            uint32_t off = (uint32_t)row * 1024 + cc * 16;
            const __half* src = g_B + (size_t)(krow0 + row) * O_DIM + cc * 8;
            cpa16(dst + swzB(off), src);
        }
    };

    // ---- A generation for i-block ib: tanh + Legendre recurrence -> 8 planes ----
    auto gen_A = [&](int ib) {
        const int row = tid >> 2;
        const int q   = tid & 3;              // 16-elem chunk within KBLK
        const float* xr = x + (size_t)(r0 + row) * I_DIM + ib * KBLK + q * 16;
        float t[16], pm1[16], pm2[16];
        #pragma unroll
        for (int c = 0; c < 4; c++) {
            float4 v = reinterpret_cast<const float4*>(xr)[c];
            t[4*c+0] = fast_tanh(v.x); t[4*c+1] = fast_tanh(v.y);
            t[4*c+2] = fast_tanh(v.z); t[4*c+3] = fast_tanh(v.w);
        }
        #pragma unroll
        for (int e = 0; e < 16; e++) { pm2[e] = 1.f; pm1[e] = t[e]; }
        const uint32_t off0 = (uint32_t)row * 128 + q * 32;
        #pragma unroll
        for (int d = 1; d <= NDEG; d++) {
            float pc[16];
            if (d == 1) {
                #pragma unroll
                for (int e = 0; e < 16; e++) pc[e] = pm1[e];
            } else {
                const float c1 = (2.f * d - 1.f) / (float)d;
                const float c2 = (d - 1.f) / (float)d;
                #pragma unroll
                for (int e = 0; e < 16; e++) pc[e] = c1 * t[e] * pm1[e] - c2 * pm2[e];
                #pragma unroll
                for (int e = 0; e < 16; e++) { pm2[e] = pm1[e]; pm1[e] = pc[e]; }
            }
            uint32_t h[8];
            #pragma unroll
            for (int p = 0; p < 8; p++) {
                __half2 hh = __floats2half2_rn(pc[2*p], pc[2*p+1]);
                h[p] = *reinterpret_cast<uint32_t*>(&hh);
            }
            const uint32_t base = sbA + (uint32_t)(d - 1) * 16384;
            sts128(base + swzA(off0),      h[0], h[1], h[2], h[3]);
            sts128(base + swzA(off0 + 16), h[4], h[5], h[6], h[7]);
        }
    };

    // fp32 accumulators: 2 m16 x 16 n8 x 4
    float acc[2][16][4];
    #pragma unroll
    for (int a = 0; a < 2; a++)
        #pragma unroll
        for (int b = 0; b < 16; b++)
            #pragma unroll
            for (int c = 0; c < 4; c++) acc[a][b][c] = 0.f;

    // prime the 3-stage ring
    prefetch_B(0); cpa_commit();
    prefetch_B(1); cpa_commit();
    prefetch_B(2); cpa_commit();

    for (int t = 0; t < NTILES; t++) {
        if ((t & 15) == 0) gen_A(t >> 4);     // safe: post-MMA sync of t-1 done

        cpa_wait2();                           // tile t arrived (3 groups in flight max)
        __syncthreads();                       // B(t) + A(ib) visible to all warps

        const int jbase = (t & 1) * 2;         // k16 offset within A plane
        const uint32_t Abase = sbA + (uint32_t)((t >> 1) & 7) * 16384;
        const uint32_t Bbase = sbB + (uint32_t)(t % B_STAGES) * 32768;

        #pragma unroll
        for (int jl = 0; jl < 2; jl++) {       // k16 steps within k32 tile
            uint32_t a0[4], a1[4];
            {
                uint32_t off0 = (uint32_t)(warp_m * 32 + la_row) * 128 +
                                ((jbase + jl) * 16 + la_hi * 8) * 2;
                ldsm_x4(a0[0], a0[1], a0[2], a0[3], Abase + swzA(off0));
                ldsm_x4(a1[0], a1[1], a1[2], a1[3], Abase + swzA(off0 + 16 * 128));
            }
            #pragma unroll
            for (int nb = 0; nb < 8; nb++) {   // n16 chunks over 128-col slab
                uint32_t b0, b1, b2, b3;
                uint32_t boff = (uint32_t)(jl * 16 + la_row) * 1024 +
                                (warp_n * 128 + nb * 16 + la_hi * 8) * 2;
                ldsm_x4_t(b0, b1, b2, b3, Bbase + swzB(boff));
                float* c00 = acc[0][2 * nb];
                float* c01 = acc[0][2 * nb + 1];
                float* c10 = acc[1][2 * nb];
                float* c11 = acc[1][2 * nb + 1];
                mma16816(c00[0], c00[1], c00[2], c00[3], a0[0], a0[1], a0[2], a0[3], b0, b1);
                mma16816(c01[0], c01[1], c01[2], c01[3], a0[0], a0[1], a0[2], a0[3], b2, b3);
                mma16816(c10[0], c10[1], c10[2], c10[3], a1[0], a1[1], a1[2], a1[3], b0, b1);
                mma16816(c11[0], c11[1], c11[2], c11[3], a1[0], a1[1], a1[2], a1[3], b2, b3);
            }
        }
        __syncthreads();                       // everyone done with stage t%3
        if (t + B_STAGES < NTILES) prefetch_B(t + B_STAGES);
        cpa_commit();                          // uniform group count (may be empty)
    }

    // ---- epilogue: unscale, add d=0 bias, store fp32 ----
    {
        const int g  = lid >> 2;
        const int tg = lid & 3;
        #pragma unroll
        for (int mt = 0; mt < 2; mt++) {
            const int rbase = r0 + warp_m * 32 + mt * 16 + g;
            #pragma unroll
            for (int nt = 0; nt < 16; nt++) {
                const int col = warp_n * 128 + nt * 8 + tg * 2;
                const float bz0 = g_bias[col];
                const float bz1 = g_bias[col + 1];
                float2 v;
                v.x = acc[mt][nt][0] * B_INVSCALE + bz0;
                v.y = acc[mt][nt][1] * B_INVSCALE + bz1;
                *reinterpret_cast<float2*>(out + (size_t)rbase * O_DIM + col) = v;
                v.x = acc[mt][nt][2] * B_INVSCALE + bz0;
                v.y = acc[mt][nt][3] * B_INVSCALE + bz1;
                *reinterpret_cast<float2*>(out + (size_t)(rbase + 8) * O_DIM + col) = v;
            }
        }
    }
}

// ---------------- launch ----------------
extern "C" void kernel_launch(void* const* d_in, const int* in_sizes, int n_in,
                              void* d_out, int out_size) {
    const float* x = (const float*)d_in[0];
    const float* C = (const float*)d_in[1];
    float* out = (float*)d_out;

    prep_b_kernel<<<(I_DIM * O_DIM) / 256, 256>>>(C);
    bias_kernel<<<(O_DIM * 32) / 256, 256>>>(C);

    cudaFuncSetAttribute(legendre_main, cudaFuncAttributeMaxDynamicSharedMemorySize, SMEM_BYTES);
    legendre_main<<<16384 / M_TILE, THREADS, SMEM_BYTES>>>(x, out);
}

// round 5
// speedup vs baseline: 2.5533x; 2.5533x over previous
#include <cuda_runtime.h>
#include <cuda_fp16.h>
#include <cstdint>

#define DI __device__ __forceinline__

// ---------------- problem constants ----------------
namespace {
constexpr int I_DIM   = 512;
constexpr int O_DIM   = 512;
constexpr int NDEG    = 8;               // degrees 1..8 in the GEMM; d=0 -> bias
constexpr int KTOT    = NDEG * I_DIM;    // 4096, k = i*8 + (d-1)
constexpr int M_DIM   = 16384;
constexpr int M_TILE  = 128;
constexpr int N_TILE  = 128;
constexpr int KBLK    = 64;              // k-tile
constexpr int NKT     = KTOT / KBLK;     // 64
constexpr int STAGES  = 3;
constexpr int THREADS = 256;             // 8 warps: warp_m = wid&3, warp_n = wid>>2

constexpr float B_SCALE    = 512.0f;
constexpr float B_INVSCALE = 1.0f / 512.0f;

// per stage: A 128x128B = 16384, B 64x256B = 16384
constexpr int STAGE_BYTES = 32768;
constexpr int SMEM_BYTES  = STAGES * STAGE_BYTES + 1024;   // 99328 -> 2 CTAs/SM
}

// ---------------- device scratch ----------------
__device__ __align__(128) __half g_A[(size_t)M_DIM * KTOT];  // A[m][k], 134 MB
__device__ __align__(128) __half g_B[KTOT * O_DIM];          // B[k][n], pre-scaled by 512
__device__ float g_bias[O_DIM];

// ---------------- helpers ----------------
DI uint32_t smem_u32(const void* p) {
    uint32_t a;
    asm("{ .reg .u64 t; cvta.to.shared.u64 t, %1; cvt.u32.u64 %0, t; }" : "=r"(a) : "l"(p));
    return a;
}
DI uint32_t swzA(uint32_t off) { return off ^ ((off >> 3) & 0x70); } // 128B rows
DI uint32_t swzB(uint32_t off) { return off ^ ((off >> 4) & 0x70); } // 256B rows

DI void cpa16(uint32_t dst, const void* src) {
    asm volatile("cp.async.cg.shared.global [%0], [%1], 16;" :: "r"(dst), "l"(src) : "memory");
}
DI void cpa_commit() { asm volatile("cp.async.commit_group;" ::: "memory"); }
DI void cpa_wait2()  { asm volatile("cp.async.wait_group 2;" ::: "memory"); }

DI void ldsm_x4(uint32_t& r0, uint32_t& r1, uint32_t& r2, uint32_t& r3, uint32_t addr) {
    asm volatile("ldmatrix.sync.aligned.m8n8.x4.shared.b16 {%0,%1,%2,%3}, [%4];"
                 : "=r"(r0), "=r"(r1), "=r"(r2), "=r"(r3) : "r"(addr));
}
DI void ldsm_x4_t(uint32_t& r0, uint32_t& r1, uint32_t& r2, uint32_t& r3, uint32_t addr) {
    asm volatile("ldmatrix.sync.aligned.m8n8.x4.trans.shared.b16 {%0,%1,%2,%3}, [%4];"
                 : "=r"(r0), "=r"(r1), "=r"(r2), "=r"(r3) : "r"(addr));
}
DI void mma16816(float& c0, float& c1, float& c2, float& c3,
                 uint32_t a0, uint32_t a1, uint32_t a2, uint32_t a3,
                 uint32_t b0, uint32_t b1) {
    asm volatile("mma.sync.aligned.m16n8k16.row.col.f32.f16.f16.f32 "
                 "{%0,%1,%2,%3}, {%4,%5,%6,%7}, {%8,%9}, {%0,%1,%2,%3};"
                 : "+f"(c0), "+f"(c1), "+f"(c2), "+f"(c3)
                 : "r"(a0), "r"(a1), "r"(a2), "r"(a3), "r"(b0), "r"(b1));
}

// tanh via ex2/rcp: abs err ~1e-6, << fp16 feature quantization
DI float fast_tanh(float v) {
    float f = fminf(fmaxf(v, -15.f), 15.f) * 2.8853900817779268f; // 2*log2(e)
    float e; asm("ex2.approx.f32 %0, %1;" : "=f"(e) : "f"(f));
    float r; asm("rcp.approx.f32 %0, %1;" : "=f"(r) : "f"(e + 1.f));
    return (e - 1.f) * r;
}

// ---------------- prologue kernels ----------------
// C layout: C[i][n][d], 9 floats per (i,n). B[k][n], k = i*8 + (d-1), scaled.
__global__ void prep_b_kernel(const float* __restrict__ C) {
    int tid = blockIdx.x * blockDim.x + threadIdx.x;   // one (i,n) each
    int n = tid & (O_DIM - 1);
    int i = tid >> 9;
    const float* src = C + ((size_t)i * O_DIM + n) * 9;
    #pragma unroll
    for (int d = 1; d <= NDEG; d++)
        g_B[(size_t)(i * 8 + d - 1) * O_DIM + n] = __float2half_rn(src[d] * B_SCALE);
}
__global__ void bias_kernel(const float* __restrict__ C) {
    int gw  = (blockIdx.x * blockDim.x + threadIdx.x) >> 5;
    int lid = threadIdx.x & 31;
    float s = 0.f;
    for (int i = lid; i < I_DIM; i += 32)
        s += C[((size_t)i * O_DIM + gw) * 9];
    #pragma unroll
    for (int o = 16; o; o >>= 1) s += __shfl_xor_sync(0xffffffffu, s, o);
    if (lid == 0) g_bias[gw] = s;
}

// gen: one thread per (m, i): tanh + Legendre -> 8 fp16, one 16B store
__global__ void __launch_bounds__(256) gen_a_kernel(const float* __restrict__ x) {
    int tid = blockIdx.x * blockDim.x + threadIdx.x;   // 0 .. 16384*512-1
    float t = fast_tanh(x[tid]);                        // x is [m][i] contiguous
    int i = tid & (I_DIM - 1);
    int m = tid >> 9;

    float pm2 = 1.f, pm1 = t;
    __half h[8];
    h[0] = __float2half_rn(t);
    #pragma unroll
    for (int d = 2; d <= NDEG; d++) {
        const float c1 = (2.f * d - 1.f) / (float)d;
        const float c2 = (d - 1.f) / (float)d;
        float pc = c1 * t * pm1 - c2 * pm2;
        pm2 = pm1; pm1 = pc;
        h[d - 1] = __float2half_rn(pc);
    }
    uint4 v;
    v.x = *reinterpret_cast<uint32_t*>(&h[0]);
    v.y = *reinterpret_cast<uint32_t*>(&h[2]);
    v.z = *reinterpret_cast<uint32_t*>(&h[4]);
    v.w = *reinterpret_cast<uint32_t*>(&h[6]);
    *reinterpret_cast<uint4*>(g_A + (size_t)m * KTOT + i * 8) = v;
}

// ---------------- GEMM kernel ----------------
__global__ void __launch_bounds__(THREADS, 2)
gemm_main(float* __restrict__ out) {
    extern __shared__ char smem_raw[];
    const uint32_t sb = (smem_u32(smem_raw) + 1023u) & ~1023u;

    const int tid = threadIdx.x;
    const int lid = tid & 31;
    const int wid = tid >> 5;
    const int warp_m = wid & 3;        // 32-row slab
    const int warp_n = wid >> 2;       // 0..1 -> 64-col slab
    const int n0 = blockIdx.x * N_TILE;   // x fastest: 4 N-CTAs share A tile in L2
    const int r0 = blockIdx.y * M_TILE;

    const int la_row = lid & 15;
    const int la_hi  = lid >> 4;

    // tile t (k64): A 128 rows x 128B, B 64 rows x 256B, stage t%3
    auto prefetch = [&](int t) {
        const uint32_t stg = sb + (uint32_t)(t % STAGES) * STAGE_BYTES;
        const int k0 = t * KBLK;
        #pragma unroll
        for (int q = 0; q < 4; q++) {   // A: 1024 chunks
            int ch  = tid + q * THREADS;
            int row = ch >> 3, cc = ch & 7;
            uint32_t off = (uint32_t)row * 128 + cc * 16;
            cpa16(stg + swzA(off), g_A + (size_t)(r0 + row) * KTOT + k0 + cc * 8);
        }
        #pragma unroll
        for (int q = 0; q < 4; q++) {   // B: 1024 chunks
            int ch  = tid + q * THREADS;
            int row = ch >> 4, cc = ch & 15;
            uint32_t off = (uint32_t)row * 256 + cc * 16;
            cpa16(stg + 16384 + swzB(off), g_B + (size_t)(k0 + row) * O_DIM + n0 + cc * 8);
        }
    };

    float acc[2][8][4];
    #pragma unroll
    for (int a = 0; a < 2; a++)
        #pragma unroll
        for (int b = 0; b < 8; b++)
            #pragma unroll
            for (int c = 0; c < 4; c++) acc[a][b][c] = 0.f;

    prefetch(0); cpa_commit();
    prefetch(1); cpa_commit();
    prefetch(2); cpa_commit();

    for (int t = 0; t < NKT; t++) {
        cpa_wait2();
        __syncthreads();                       // tile t visible to all warps

        const uint32_t Abase = sb + (uint32_t)(t % STAGES) * STAGE_BYTES;
        const uint32_t Bbase = Abase + 16384;

        #pragma unroll
        for (int j = 0; j < 4; j++) {          // k16 steps
            uint32_t a0[4], a1[4];
            {
                uint32_t off0 = (uint32_t)(warp_m * 32 + la_row) * 128 + (j * 16 + la_hi * 8) * 2;
                ldsm_x4(a0[0], a0[1], a0[2], a0[3], Abase + swzA(off0));
                ldsm_x4(a1[0], a1[1], a1[2], a1[3], Abase + swzA(off0 + 16 * 128));
            }
            #pragma unroll
            for (int nb = 0; nb < 4; nb++) {
                uint32_t b0, b1, b2, b3;
                uint32_t boff = (uint32_t)(j * 16 + la_row) * 256 +
                                (warp_n * 64 + nb * 16 + la_hi * 8) * 2;
                ldsm_x4_t(b0, b1, b2, b3, Bbase + swzB(boff));
                float* c00 = acc[0][2 * nb];
                float* c01 = acc[0][2 * nb + 1];
                float* c10 = acc[1][2 * nb];
                float* c11 = acc[1][2 * nb + 1];
                mma16816(c00[0], c00[1], c00[2], c00[3], a0[0], a0[1], a0[2], a0[3], b0, b1);
                mma16816(c01[0], c01[1], c01[2], c01[3], a0[0], a0[1], a0[2], a0[3], b2, b3);
                mma16816(c10[0], c10[1], c10[2], c10[3], a1[0], a1[1], a1[2], a1[3], b0, b1);
                mma16816(c11[0], c11[1], c11[2], c11[3], a1[0], a1[1], a1[2], a1[3], b2, b3);
            }
        }
        __syncthreads();                       // all warps done with stage t%3
        if (t + STAGES < NKT) prefetch(t + STAGES);
        cpa_commit();                          // uniform group count (may be empty)
    }

    // ---- epilogue: unscale, add d=0 bias, store fp32 ----
    {
        const int g  = lid >> 2;
        const int tg = lid & 3;
        #pragma unroll
        for (int mt = 0; mt < 2; mt++) {
            const int rbase = r0 + warp_m * 32 + mt * 16 + g;
            #pragma unroll
            for (int nt = 0; nt < 8; nt++) {
                const int col = n0 + warp_n * 64 + nt * 8 + tg * 2;
                const float bz0 = g_bias[col];
                const float bz1 = g_bias[col + 1];
                float2 v;
                v.x = acc[mt][nt][0] * B_INVSCALE + bz0;
                v.y = acc[mt][nt][1] * B_INVSCALE + bz1;
                *reinterpret_cast<float2*>(out + (size_t)rbase * O_DIM + col) = v;
                v.x = acc[mt][nt][2] * B_INVSCALE + bz0;
                v.y = acc[mt][nt][3] * B_INVSCALE + bz1;
                *reinterpret_cast<float2*>(out + (size_t)(rbase + 8) * O_DIM + col) = v;
            }
        }
    }
}

// ---------------- launch ----------------
extern "C" void kernel_launch(void* const* d_in, const int* in_sizes, int n_in,
                              void* d_out, int out_size) {
    const float* x = (const float*)d_in[0];
    const float* C = (const float*)d_in[1];
    float* out = (float*)d_out;

    prep_b_kernel<<<(I_DIM * O_DIM) / 256, 256>>>(C);
    bias_kernel<<<(O_DIM * 32) / 256, 256>>>(C);
    gen_a_kernel<<<(M_DIM * I_DIM) / 256, 256>>>(x);

    cudaFuncSetAttribute(gemm_main, cudaFuncAttributeMaxDynamicSharedMemorySize, SMEM_BYTES);
    dim3 grid(O_DIM / N_TILE, M_DIM / M_TILE);   // (4, 128), n fastest
    gemm_main<<<grid, THREADS, SMEM_BYTES>>>(out);
}

// round 8
// speedup vs baseline: 2.7650x; 1.0829x over previous
#include <cuda_runtime.h>
#include <cuda_fp16.h>
#include <cstdint>

#define DI __device__ __forceinline__

// ---------------- problem constants ----------------
namespace {
constexpr int I_DIM   = 512;
constexpr int O_DIM   = 512;
constexpr int NDEG    = 8;               // degrees 1..8 in the GEMM; d=0 -> bias
constexpr int KTOT    = NDEG * I_DIM;    // 4096, k = i*8 + (d-1)
constexpr int M_DIM   = 16384;
constexpr int M_TILE  = 128;
constexpr int N_TILE  = 64;
constexpr int KBLK    = 64;              // k-tile
constexpr int NKT     = KTOT / KBLK;     // 64
constexpr int STAGES  = 3;
constexpr int THREADS = 256;             // 8 warps: warp_m = wid&3 (32 rows), warp_n = wid>>2 (32 cols)

constexpr float B_SCALE    = 512.0f;
constexpr float B_INVSCALE = 1.0f / 512.0f;

// per stage: A 128 rows x 128B = 16384 ; B 64 rows x 128B = 8192
constexpr int A_STAGE     = 16384;
constexpr int B_STAGE     = 8192;
constexpr int STAGE_BYTES = A_STAGE + B_STAGE;            // 24576
constexpr int SMEM_BYTES  = STAGES * STAGE_BYTES + 1024;  // 74752 -> 3 CTAs/SM
}

// ---------------- device scratch ----------------
__device__ __align__(128) __half g_A[(size_t)M_DIM * KTOT];  // A[m][k], 134 MB
__device__ __align__(128) __half g_B[KTOT * O_DIM];          // B[k][n], pre-scaled by 512
__device__ float g_bias[O_DIM];

// ---------------- helpers ----------------
DI uint32_t smem_u32(const void* p) {
    uint32_t a;
    asm("{ .reg .u64 t; cvta.to.shared.u64 t, %1; cvt.u32.u64 %0, t; }" : "=r"(a) : "l"(p));
    return a;
}
DI uint32_t swz(uint32_t off) { return off ^ ((off >> 3) & 0x70); }   // 128B rows

DI void cpa16(uint32_t dst, const void* src) {
    asm volatile("cp.async.cg.shared.global [%0], [%1], 16;" :: "r"(dst), "l"(src) : "memory");
}
DI void cpa_commit() { asm volatile("cp.async.commit_group;" ::: "memory"); }
DI void cpa_wait1()  { asm volatile("cp.async.wait_group 1;" ::: "memory"); }

DI void ldsm_x4(uint32_t& r0, uint32_t& r1, uint32_t& r2, uint32_t& r3, uint32_t addr) {
    asm volatile("ldmatrix.sync.aligned.m8n8.x4.shared.b16 {%0,%1,%2,%3}, [%4];"
                 : "=r"(r0), "=r"(r1), "=r"(r2), "=r"(r3) : "r"(addr));
}
DI void ldsm_x4_t(uint32_t& r0, uint32_t& r1, uint32_t& r2, uint32_t& r3, uint32_t addr) {
    asm volatile("ldmatrix.sync.aligned.m8n8.x4.trans.shared.b16 {%0,%1,%2,%3}, [%4];"
                 : "=r"(r0), "=r"(r1), "=r"(r2), "=r"(r3) : "r"(addr));
}
DI void mma16816(float& c0, float& c1, float& c2, float& c3,
                 uint32_t a0, uint32_t a1, uint32_t a2, uint32_t a3,
                 uint32_t b0, uint32_t b1) {
    asm volatile("mma.sync.aligned.m16n8k16.row.col.f32.f16.f16.f32 "
                 "{%0,%1,%2,%3}, {%4,%5,%6,%7}, {%8,%9}, {%0,%1,%2,%3};"
                 : "+f"(c0), "+f"(c1), "+f"(c2), "+f"(c3)
                 : "r"(a0), "r"(a1), "r"(a2), "r"(a3), "r"(b0), "r"(b1));
}

// tanh via ex2/rcp: abs err ~1e-6, << fp16 feature quantization
DI float fast_tanh(float v) {
    float f = fminf(fmaxf(v, -15.f), 15.f) * 2.8853900817779268f; // 2*log2(e)
    float e; asm("ex2.approx.f32 %0, %1;" : "=f"(e) : "f"(f));
    float r; asm("rcp.approx.f32 %0, %1;" : "=f"(r) : "f"(e + 1.f));
    return (e - 1.f) * r;
}

// ---------------- prologue kernels ----------------
// C layout: C[i][n][d], 9 floats per (i,n). B[k][n], k = i*8 + (d-1), scaled.
__global__ void prep_b_kernel(const float* __restrict__ C) {
    int tid = blockIdx.x * blockDim.x + threadIdx.x;   // one (i,n) each
    int n = tid & (O_DIM - 1);
    int i = tid >> 9;
    const float* src = C + ((size_t)i * O_DIM + n) * 9;
    #pragma unroll
    for (int d = 1; d <= NDEG; d++)
        g_B[(size_t)(i * 8 + d - 1) * O_DIM + n] = __float2half_rn(src[d] * B_SCALE);
}
__global__ void bias_kernel(const float* __restrict__ C) {
    int gw  = (blockIdx.x * blockDim.x + threadIdx.x) >> 5;
    int lid = threadIdx.x & 31;
    float s = 0.f;
    for (int i = lid; i < I_DIM; i += 32)
        s += C[((size_t)i * O_DIM + gw) * 9];
    #pragma unroll
    for (int o = 16; o; o >>= 1) s += __shfl_xor_sync(0xffffffffu, s, o);
    if (lid == 0) g_bias[gw] = s;
}

// gen: one thread per (m, i): tanh + Legendre -> 8 fp16, one 16B store
__global__ void __launch_bounds__(256) gen_a_kernel(const float* __restrict__ x) {
    int tid = blockIdx.x * blockDim.x + threadIdx.x;   // 0 .. 16384*512-1
    float t = fast_tanh(x[tid]);                        // x is [m][i] contiguous
    int i = tid & (I_DIM - 1);
    int m = tid >> 9;

    float pm2 = 1.f, pm1 = t;
    __half h[8];
    h[0] = __float2half_rn(t);
    #pragma unroll
    for (int d = 2; d <= NDEG; d++) {
        const float c1 = (2.f * d - 1.f) / (float)d;
        const float c2 = (d - 1.f) / (float)d;
        float pc = c1 * t * pm1 - c2 * pm2;
        pm2 = pm1; pm1 = pc;
        h[d - 1] = __float2half_rn(pc);
    }
    uint4 v;
    v.x = *reinterpret_cast<uint32_t*>(&h[0]);
    v.y = *reinterpret_cast<uint32_t*>(&h[2]);
    v.z = *reinterpret_cast<uint32_t*>(&h[4]);
    v.w = *reinterpret_cast<uint32_t*>(&h[6]);
    *reinterpret_cast<uint4*>(g_A + (size_t)m * KTOT + i * 8) = v;
}

// ---------------- GEMM kernel ----------------
__global__ void __launch_bounds__(THREADS, 3)
gemm_main(float* __restrict__ out) {
    extern __shared__ char smem_raw[];
    const uint32_t sb = (smem_u32(smem_raw) + 1023u) & ~1023u;

    const int tid = threadIdx.x;
    const int lid = tid & 31;
    const int wid = tid >> 5;
    const int warp_m = wid & 3;           // 32-row slab
    const int warp_n = wid >> 2;          // 0..1 -> 32-col slab
    const int n0 = blockIdx.x * N_TILE;   // x fastest: 8 N-CTAs share an A tile in L2
    const int r0 = blockIdx.y * M_TILE;

    const int la_row = lid & 15;
    const int la_hi  = lid >> 4;

    // tile t (k64): A 128 rows x 128B, B 64 rows x 128B, stage t%3
    auto prefetch = [&](int t) {
        const uint32_t stg = sb + (uint32_t)(t % STAGES) * STAGE_BYTES;
        const int k0 = t * KBLK;
        #pragma unroll
        for (int q = 0; q < 4; q++) {       // A: 1024 x 16B chunks
            int ch  = tid + q * THREADS;
            int row = ch >> 3, cc = ch & 7;
            uint32_t off = (uint32_t)row * 128 + cc * 16;
            cpa16(stg + swz(off), g_A + (size_t)(r0 + row) * KTOT + k0 + cc * 8);
        }
        #pragma unroll
        for (int q = 0; q < 2; q++) {       // B: 512 x 16B chunks
            int ch  = tid + q * THREADS;
            int row = ch >> 3, cc = ch & 7;
            uint32_t off = (uint32_t)row * 128 + cc * 16;
            cpa16(stg + A_STAGE + swz(off), g_B + (size_t)(k0 + row) * O_DIM + n0 + cc * 8);
        }
        cpa_commit();
    };

    float acc[2][4][4];
    #pragma unroll
    for (int a = 0; a < 2; a++)
        #pragma unroll
        for (int b = 0; b < 4; b++)
            #pragma unroll
            for (int c = 0; c < 4; c++) acc[a][b][c] = 0.f;

    prefetch(0);
    prefetch(1);

    for (int t = 0; t < NKT; t++) {
        cpa_wait1();                       // tile t landed (t+1 may still be in flight)
        __syncthreads();                   // all warps see tile t; all done reading stage (t-1)%3

        // refill stage (t+2)%3 == (t-1)%3, just released by the barrier above
        if (t + 2 < NKT) prefetch(t + 2);
        else             cpa_commit();     // keep group count uniform

        const uint32_t Abase = sb + (uint32_t)(t % STAGES) * STAGE_BYTES;
        const uint32_t Bbase = Abase + A_STAGE;

        #pragma unroll
        for (int j = 0; j < 4; j++) {      // k16 steps
            uint32_t a0[4], a1[4];
            {
                uint32_t off0 = (uint32_t)(warp_m * 32 + la_row) * 128 + (j * 16 + la_hi * 8) * 2;
                ldsm_x4(a0[0], a0[1], a0[2], a0[3], Abase + swz(off0));
                ldsm_x4(a1[0], a1[1], a1[2], a1[3], Abase + swz(off0 + 16 * 128));
            }
            #pragma unroll
            for (int nb = 0; nb < 2; nb++) {
                uint32_t b0, b1, b2, b3;
                uint32_t boff = (uint32_t)(j * 16 + la_row) * 128 +
                                (warp_n * 32 + nb * 16 + la_hi * 8) * 2;
                ldsm_x4_t(b0, b1, b2, b3, Bbase + swz(boff));
                float* c00 = acc[0][2 * nb];
                float* c01 = acc[0][2 * nb + 1];
                float* c10 = acc[1][2 * nb];
                float* c11 = acc[1][2 * nb + 1];
                mma16816(c00[0], c00[1], c00[2], c00[3], a0[0], a0[1], a0[2], a0[3], b0, b1);
                mma16816(c01[0], c01[1], c01[2], c01[3], a0[0], a0[1], a0[2], a0[3], b2, b3);
                mma16816(c10[0], c10[1], c10[2], c10[3], a1[0], a1[1], a1[2], a1[3], b0, b1);
                mma16816(c11[0], c11[1], c11[2], c11[3], a1[0], a1[1], a1[2], a1[3], b2, b3);
            }
        }
    }

    // ---- epilogue: unscale, add d=0 bias, store fp32 ----
    {
        const int g  = lid >> 2;
        const int tg = lid & 3;
        #pragma unroll
        for (int mt = 0; mt < 2; mt++) {
            const int rbase = r0 + warp_m * 32 + mt * 16 + g;
            #pragma unroll
            for (int nt = 0; nt < 4; nt++) {
                const int col = n0 + warp_n * 32 + nt * 8 + tg * 2;
                const float bz0 = g_bias[col];
                const float bz1 = g_bias[col + 1];
                float2 v;
                v.x = acc[mt][nt][0] * B_INVSCALE + bz0;
                v.y = acc[mt][nt][1] * B_INVSCALE + bz1;
                *reinterpret_cast<float2*>(out + (size_t)rbase * O_DIM + col) = v;
                v.x = acc[mt][nt][2] * B_INVSCALE + bz0;
                v.y = acc[mt][nt][3] * B_INVSCALE + bz1;
                *reinterpret_cast<float2*>(out + (size_t)(rbase + 8) * O_DIM + col) = v;
            }
        }
    }
}

// ---------------- launch ----------------
extern "C" void kernel_launch(void* const* d_in, const int* in_sizes, int n_in,
                              void* d_out, int out_size) {
    const float* x = (const float*)d_in[0];
    const float* C = (const float*)d_in[1];
    float* out = (float*)d_out;

    prep_b_kernel<<<(I_DIM * O_DIM) / 256, 256>>>(C);
    bias_kernel<<<(O_DIM * 32) / 256, 256>>>(C);
    gen_a_kernel<<<(M_DIM * I_DIM) / 256, 256>>>(x);

    cudaFuncSetAttribute(gemm_main, cudaFuncAttributeMaxDynamicSharedMemorySize, SMEM_BYTES);
    dim3 grid(O_DIM / N_TILE, M_DIM / M_TILE);   // (8, 128), n fastest
    gemm_main<<<grid, THREADS, SMEM_BYTES>>>(out);
}